// round 12
// baseline (speedup 1.0000x reference)
#include <cuda_runtime.h>

#define N_ROWS   1000000
#define N_FEAT   100
#define N_BINS   256
#define GRID_B   148
#define ROWS_PER 6784            // all blocks: row count multiple of 32 (nsc = 212 or 86)

#define HIST_BYTES  204800       // 3 warps*256*32*8 + 1 warp*256*4*8 (float2 per bin)
#define STAGE_BYTES 12800        // 32 rows * 100 ints per buffer
#define SMEM_BYTES  (HIST_BYTES + 2*STAGE_BYTES + 2*256)   // 230912

// Per-block partial histograms: [block][feature][bin] as float2 (g,h).
__device__ float2 g_part2[GRID_B * N_FEAT * N_BINS];
// Stage-1 reduced partials: [feature][quarter][bin] as float2 (g,h).
__device__ float2 g_red[N_FEAT * 4 * N_BINS];

__global__ __launch_bounds__(256, 1)
void hist_kernel(const int* __restrict__ X,
                 const float* __restrict__ grad,
                 const float* __restrict__ hess)
{
    extern __shared__ unsigned char smem_raw[];

    const int tid  = threadIdx.x;
    const int w    = tid >> 5;
    const int lane = tid & 31;
    const bool isProd = (w >= 4);            // warps 4-7 produce, 0-3 consume
    const int  f      = tid;                 // consumer: feature owned
    const bool act    = (!isProd) && (f < N_FEAT);

    // Consumer histogram: transposed, element (lane, b) at cbase + (b<<sh) + lane*8.
    // Warps 0-2: 32 lanes (bank64 = lane, conflict-free). Warp 3: 4 active lanes.
    const int      sh    = (w < 3) ? 8 : 5;
    const unsigned cbase = (w < 3) ? (unsigned)(w * 65536) : 196608u;
    unsigned char* const histBase = smem_raw + cbase + lane * 8;

    // Staging buffers.
    int*    const stageB[2] = { (int*)(smem_raw + HIST_BYTES),
                                (int*)(smem_raw + HIST_BYTES + STAGE_BYTES) };
    float2* const stageV[2] = { (float2*)(smem_raw + HIST_BYTES + 2*STAGE_BYTES),
                                (float2*)(smem_raw + HIST_BYTES + 2*STAGE_BYTES + 256) };

    // ---- zero histogram region ----
    {
        float4 z = make_float4(0.f, 0.f, 0.f, 0.f);
        float4* s4 = reinterpret_cast<float4*>(smem_raw);
        for (int i = tid; i < HIST_BYTES / 16; i += 256) s4[i] = z;
    }
    __syncthreads();

    const int rowStart = blockIdx.x * ROWS_PER;
    const int rowEnd   = min(rowStart + ROWS_PER, N_ROWS);
    const int nsc      = (rowEnd - rowStart) >> 5;   // exact

    // ---- producer: fill staging buffer b with superchunk sc ----
    auto produce = [&](int sc, int b) {
        int*    sb = stageB[b];
        float2* sv = stageV[b];
        const int pw    = w - 4;
        const int rbase = rowStart + sc * 32;
        if (lane < 25) {
#pragma unroll
            for (int i = 0; i < 8; ++i) {
                const int row = pw * 8 + i;
                const int4* src = reinterpret_cast<const int4*>(X + (rbase + row) * N_FEAT);
                int4 v = __ldg(src + lane);                        // 16B of the 400B row
                *reinterpret_cast<int4*>(sb + row * N_FEAT + lane * 4) = v;
            }
        }
        if (pw == 3) {
            float gv = __ldg(grad + rbase + lane);
            float hv = __ldg(hess + rbase + lane);
            sv[lane] = make_float2(gv, hv);
        }
    };

    // ---- consumer: process staged superchunk in buffer b ----
    auto consume = [&](int b) {
        const int*    sb = stageB[b];
        const float2* sv = stageV[b];
#pragma unroll
        for (int c = 0; c < 8; ++c) {
            const int r = 4 * c;
            int b0 = 0, b1 = 0, b2 = 0, b3 = 0;
            if (act) {
                b0 = sb[(r + 0) * N_FEAT + f];   // lanes = consecutive features: conflict-free
                b1 = sb[(r + 1) * N_FEAT + f];
                b2 = sb[(r + 2) * N_FEAT + f];
                b3 = sb[(r + 3) * N_FEAT + f];
            }
            const float4 v01 = *reinterpret_cast<const float4*>(sv + r);      // g0,h0,g1,h1
            const float4 v23 = *reinterpret_cast<const float4*>(sv + r + 2);  // g2,h2,g3,h3
            // Originals (never mutated) — merge additions MUST use these, not the
            // running sums, or triple-duplicates double-count (R8 bug).
            const float2 O0 = make_float2(v01.x, v01.y);
            const float2 O1 = make_float2(v01.z, v01.w);
            const float2 O2 = make_float2(v23.x, v23.y);
            float2 G0 = O0, G1 = O1;
            float2 G2 = O2, G3 = make_float2(v23.z, v23.w);

            const bool p01 = (b0 == b1), p02 = (b0 == b2), p03 = (b0 == b3);
            const bool p12 = (b1 == b2), p13 = (b1 == b3), p23 = (b2 == b3);
            if (p01) { G1.x += O0.x; G1.y += O0.y; }
            if (p02) { G2.x += O0.x; G2.y += O0.y; }
            if (p12) { G2.x += O1.x; G2.y += O1.y; }
            if (p03) { G3.x += O0.x; G3.y += O0.y; }
            if (p13) { G3.x += O1.x; G3.y += O1.y; }
            if (p23) { G3.x += O2.x; G3.y += O2.y; }
            if (p01 | p02 | p03) { G0.x = 0.f; G0.y = 0.f; }
            if (p12 | p13)       { G1.x = 0.f; G1.y = 0.f; }
            if (p23)             { G2.x = 0.f; G2.y = 0.f; }

            if (act) {
                float2* a0 = reinterpret_cast<float2*>(histBase + (((unsigned)b0) << sh));
                float2* a1 = reinterpret_cast<float2*>(histBase + (((unsigned)b1) << sh));
                float2* a2 = reinterpret_cast<float2*>(histBase + (((unsigned)b2) << sh));
                float2* a3 = reinterpret_cast<float2*>(histBase + (((unsigned)b3) << sh));
                float2 v0 = *a0, v1 = *a1, v2 = *a2, v3 = *a3;
                v0.x += G0.x; v0.y += G0.y;
                v1.x += G1.x; v1.y += G1.y;
                v2.x += G2.x; v2.y += G2.y;
                v3.x += G3.x; v3.y += G3.y;
                *a0 = v0; *a1 = v1; *a2 = v2; *a3 = v3;  // program order: last alias wins
            }
        }
    };

    // ---- pipelined main loop: producers fill sc s+1 while consumers eat sc s ----
    if (isProd) produce(0, 0);
    __syncthreads();
    for (int s = 0; s < nsc; ++s) {
        if (isProd) {
            if (s + 1 < nsc) produce(s + 1, (s + 1) & 1);
        } else {
            consume(s & 1);
        }
        __syncthreads();
    }

    // ---- dump private histogram -> global partials ----
    if (act) {
        float2* myPart = g_part2 + (blockIdx.x * N_FEAT + f) * N_BINS;
#pragma unroll 4
        for (int bb = 0; bb < N_BINS; bb += 2) {
            float2 x0 = *reinterpret_cast<float2*>(histBase + (((unsigned)bb)     << sh));
            float2 x1 = *reinterpret_cast<float2*>(histBase + (((unsigned)(bb+1)) << sh));
            *reinterpret_cast<float4*>(myPart + bb) = make_float4(x0.x, x0.y, x1.x, x1.y);
        }
    }
}

// Stage 1: 400 blocks, block (f, q) reduces 37 of the 148 partials.
__global__ __launch_bounds__(256)
void reduce1_kernel()
{
    const int f   = blockIdx.x >> 2;
    const int q   = blockIdx.x & 3;
    const int tid = threadIdx.x;

    float gs = 0.f, hs = 0.f;
    const int blk0 = q * 37;
    const float2* p = g_part2 + f * N_BINS + tid;
#pragma unroll 4
    for (int i = 0; i < 37; ++i) {
        float2 v = p[(blk0 + i) * (N_FEAT * N_BINS)];
        gs += v.x; hs += v.y;
    }
    g_red[(f * 4 + q) * N_BINS + tid] = make_float2(gs, hs);
}

// Stage 2: 100 blocks, reduce 4 quarters + inclusive scan over 256 bins.
__global__ __launch_bounds__(256)
void reduce2_kernel(float* __restrict__ out)
{
    const int f   = blockIdx.x;
    const int tid = threadIdx.x;

    float2 acc = make_float2(0.f, 0.f);
#pragma unroll
    for (int q = 0; q < 4; ++q) {
        float2 v = g_red[(f * 4 + q) * N_BINS + tid];
        acc.x += v.x; acc.y += v.y;
    }

    __shared__ float2 buf[N_BINS];
    buf[tid] = acc;
    __syncthreads();
#pragma unroll
    for (int off = 1; off < N_BINS; off <<= 1) {
        float2 t = make_float2(0.f, 0.f);
        const bool pred = (tid >= off);
        if (pred) t = buf[tid - off];
        __syncthreads();
        if (pred) { buf[tid].x += t.x; buf[tid].y += t.y; }
        __syncthreads();
    }
    float2 r = buf[tid];
    out[f * N_BINS + tid]                   = r.x;   // Gl
    out[N_FEAT * N_BINS + f * N_BINS + tid] = r.y;   // Hl
}

extern "C" void kernel_launch(void* const* d_in, const int* in_sizes, int n_in,
                              void* d_out, int out_size)
{
    const int*   X = (const int*)d_in[0];
    const float* g = (const float*)d_in[1];
    const float* h = (const float*)d_in[2];
    float* out = (float*)d_out;

    (void)cudaFuncSetAttribute(hist_kernel,
                               cudaFuncAttributeMaxDynamicSharedMemorySize, SMEM_BYTES);

    hist_kernel<<<GRID_B, 256, SMEM_BYTES>>>(X, g, h);
    reduce1_kernel<<<N_FEAT * 4, 256>>>();
    reduce2_kernel<<<N_FEAT, 256>>>(out);
}

// round 13
// speedup vs baseline: 1.4820x; 1.4820x over previous
#include <cuda_runtime.h>
#include <cstdint>

#define N_ROWS   1000000
#define N_FEAT   100
#define N_BINS   256
#define GRID_B   148
#define ROWS_PER 6784            // all blocks: rows multiple of 32 (nsc = 212 or 86, even)

#define HIST_BYTES  204800       // 2 halves * (3 warps*256*32*4 + 1 warp*256*4*4), scalar float
#define HALF_BYTES  102400
#define BINS_BYTES  12800        // 32 rows * 100 ints
#define VALS_BYTES  256          // 128 B grad + 128 B hess
#define SMEM_BYTES  (HIST_BYTES + 2*BINS_BYTES + 2*VALS_BYTES + 64)   // 230976

// Per-block partial histograms, scalar floats: [block][half][feature][bin].
__device__ float  g_part[GRID_B * 2 * N_FEAT * N_BINS];
// Stage-1 reduced partials: [feature][quarter][bin] as float2 (g,h).
__device__ float2 g_red[N_FEAT * 4 * N_BINS];

__device__ __forceinline__ uint32_t smem_u32(const void* p) {
    uint32_t a;
    asm("{ .reg .u64 t; cvta.to.shared.u64 t, %1; cvt.u32.u64 %0, t; }" : "=r"(a) : "l"(p));
    return a;
}

__device__ __forceinline__ void mbar_init(uint32_t mbar, uint32_t cnt) {
    asm volatile("mbarrier.init.shared.b64 [%0], %1;" :: "r"(mbar), "r"(cnt) : "memory");
}
__device__ __forceinline__ void mbar_expect_tx(uint32_t mbar, uint32_t tx) {
    asm volatile("mbarrier.arrive.expect_tx.shared.b64 _, [%0], %1;" :: "r"(mbar), "r"(tx) : "memory");
}
__device__ __forceinline__ void mbar_wait(uint32_t mbar, uint32_t parity) {
    uint32_t done;
    asm volatile(
        "{\n\t.reg .pred p;\n\t"
        "mbarrier.try_wait.parity.acquire.cta.shared::cta.b64 p, [%1], %2;\n\t"
        "selp.b32 %0, 1, 0, p;\n\t}"
        : "=r"(done) : "r"(mbar), "r"(parity) : "memory");
    if (!done) {
        asm volatile(
            "{\n\t.reg .pred P1;\n\t"
            "WL_%=:\n\t"
            "mbarrier.try_wait.parity.acquire.cta.shared::cta.b64 P1, [%0], %1, 0x989680;\n\t"
            "@P1 bra.uni WD_%=;\n\t"
            "bra.uni WL_%=;\n\t"
            "WD_%=:\n\t}"
            :: "r"(mbar), "r"(parity) : "memory");
    }
}
__device__ __forceinline__ void tma_bulk_g2s(uint32_t dst, const void* src, uint32_t bytes, uint32_t mbar) {
    asm volatile(
        "cp.async.bulk.shared::cta.global.mbarrier::complete_tx::bytes [%0], [%1], %2, [%3];"
        :: "r"(dst), "l"(src), "r"(bytes), "r"(mbar) : "memory");
}

__global__ __launch_bounds__(256, 1)
void hist_kernel(const int* __restrict__ X,
                 const float* __restrict__ grad,
                 const float* __restrict__ hess)
{
    extern __shared__ unsigned char smem_raw[];

    const int tid  = threadIdx.x;
    const int w    = tid >> 5;
    const int lane = tid & 31;
    const int half = w >> 2;             // 0: gradient, 1: hessian
    const int w3   = w & 3;              // warp index within half
    const int f    = tid & 127;          // feature owned by this thread
    const bool act = (f < N_FEAT);

    // Transposed warp-private histogram region: element (lane, b) at base + (b<<sh) + lane*4.
    // Full warps (w3<3): bank = lane -> conflict-free. Tail warp: 4 active lanes.
    const int      sh   = (w3 < 3) ? 7 : 4;
    const unsigned base = half * HALF_BYTES +
                          ((w3 < 3) ? (unsigned)(w3 * 32768) : 98304u);
    unsigned char* const histBase = smem_raw + base + lane * 4;

    // Staging: two bins buffers, two val buffers, two mbarriers.
    int*   const binsBuf[2] = { (int*)(smem_raw + HIST_BYTES),
                                (int*)(smem_raw + HIST_BYTES + BINS_BYTES) };
    unsigned char* const valsBuf[2] = { smem_raw + HIST_BYTES + 2*BINS_BYTES,
                                        smem_raw + HIST_BYTES + 2*BINS_BYTES + VALS_BYTES };
    const uint32_t mbar0 = smem_u32(smem_raw + HIST_BYTES + 2*BINS_BYTES + 2*VALS_BYTES);
    const uint32_t mbarA[2] = { mbar0, mbar0 + 8 };

    // ---- zero histogram region; init mbarriers ----
    {
        float4 z = make_float4(0.f, 0.f, 0.f, 0.f);
        float4* s4 = reinterpret_cast<float4*>(smem_raw);
        for (int i = tid; i < HIST_BYTES / 16; i += 256) s4[i] = z;
    }
    if (tid == 0) { mbar_init(mbarA[0], 1); mbar_init(mbarA[1], 1); }
    __syncthreads();

    const int rowStart = blockIdx.x * ROWS_PER;
    const int rowEnd   = min(rowStart + ROWS_PER, N_ROWS);
    const int nsc      = (rowEnd - rowStart) >> 5;   // exact (212 or 86)

    const unsigned char* const Xsrc = reinterpret_cast<const unsigned char*>(X + rowStart * N_FEAT);
    const unsigned char* const Gsrc = reinterpret_cast<const unsigned char*>(grad + rowStart);
    const unsigned char* const Hsrc = reinterpret_cast<const unsigned char*>(hess + rowStart);

    // ---- producer: one thread issues 3 bulk TMA copies for superchunk sc -> buffer b ----
    auto produce = [&](int sc, int b) {
        const uint32_t mb = mbarA[b];
        mbar_expect_tx(mb, BINS_BYTES + VALS_BYTES);
        tma_bulk_g2s(smem_u32(binsBuf[b]),      Xsrc + (size_t)sc * BINS_BYTES, BINS_BYTES, mb);
        tma_bulk_g2s(smem_u32(valsBuf[b]),      Gsrc + (size_t)sc * 128,        128,        mb);
        tma_bulk_g2s(smem_u32(valsBuf[b] + 128), Hsrc + (size_t)sc * 128,       128,        mb);
    };

    // ---- consumer: R2-style, bins via coalesced LDS from staging ----
    auto consume = [&](int b) {
        const int* sb = binsBuf[b];
        const float4* vp = reinterpret_cast<const float4*>(valsBuf[b] + half * 128);
#pragma unroll
        for (int c = 0; c < 8; ++c) {
            const int r = 4 * c;
            int b0 = 0, b1 = 0, b2 = 0, b3 = 0;
            if (act) {
                b0 = sb[(r + 0) * N_FEAT + f];   // lanes = consecutive features -> coalesced LDS
                b1 = sb[(r + 1) * N_FEAT + f];
                b2 = sb[(r + 2) * N_FEAT + f];
                b3 = sb[(r + 3) * N_FEAT + f];
            }
            const float4 gv = vp[c];             // rows 4c..4c+3, warp-uniform LDS.128
            const float g0 = gv.x, g1 = gv.y, g2 = gv.z, g3 = gv.w;

            // Duplicate-merge on ORIGINAL values (R8 lesson: never use running sums).
            const bool p01 = (b0 == b1), p02 = (b0 == b2), p03 = (b0 == b3);
            const bool p12 = (b1 == b2), p13 = (b1 == b3), p23 = (b2 == b3);
            float G0 = g0, G1 = g1, G2 = g2, G3 = g3;
            if (p01) G1 += g0;
            if (p02) G2 += g0;
            if (p12) G2 += g1;
            if (p03) G3 += g0;
            if (p13) G3 += g1;
            if (p23) G3 += g2;
            if (p01 | p02 | p03) G0 = 0.f;
            if (p12 | p13)       G1 = 0.f;
            if (p23)             G2 = 0.f;

            if (act) {
                float* a0 = reinterpret_cast<float*>(histBase + ((unsigned)b0 << sh));
                float* a1 = reinterpret_cast<float*>(histBase + ((unsigned)b1 << sh));
                float* a2 = reinterpret_cast<float*>(histBase + ((unsigned)b2 << sh));
                float* a3 = reinterpret_cast<float*>(histBase + ((unsigned)b3 << sh));
                float v0 = *a0, v1 = *a1, v2 = *a2, v3 = *a3;
                v0 += G0; v1 += G1; v2 += G2; v3 += G3;
                *a0 = v0; *a1 = v1; *a2 = v2; *a3 = v3;   // thread-order: last alias wins
            }
        }
    };

    // ---- pipelined main loop: TMA double-buffer, all 8 warps consume ----
    if (tid == 0) { produce(0, 0); if (nsc > 1) produce(1, 1); }
    for (int s = 0; s < nsc; ++s) {
        const int b = s & 1;
        mbar_wait(mbarA[b], (unsigned)(s >> 1) & 1);
        consume(b);
        __syncthreads();                 // all consumers done with buffer b
        if (tid == 0 && s + 2 < nsc) {
            asm volatile("fence.proxy.async.shared::cta;" ::: "memory");
            produce(s + 2, b);
        }
    }

    __syncthreads();

    // ---- dump private histogram -> global partials (STG.128) ----
    if (act) {
        float4* myPart = reinterpret_cast<float4*>(
            g_part + ((blockIdx.x * 2 + half) * N_FEAT + f) * N_BINS);
#pragma unroll 4
        for (int b = 0; b < N_BINS; b += 4) {
            float4 v;
            v.x = *reinterpret_cast<float*>(histBase + ((unsigned)(b + 0) << sh));
            v.y = *reinterpret_cast<float*>(histBase + ((unsigned)(b + 1) << sh));
            v.z = *reinterpret_cast<float*>(histBase + ((unsigned)(b + 2) << sh));
            v.w = *reinterpret_cast<float*>(histBase + ((unsigned)(b + 3) << sh));
            myPart[b >> 2] = v;
        }
    }
}

// Stage 1: 400 blocks, block (f, q) reduces 37 of the 148 partials.
__global__ __launch_bounds__(256)
void reduce1_kernel()
{
    const int f   = blockIdx.x >> 2;
    const int q   = blockIdx.x & 3;
    const int tid = threadIdx.x;

    float gs = 0.f, hs = 0.f;
    const int blk0 = q * 37;
#pragma unroll 4
    for (int i = 0; i < 37; ++i) {
        const int blk = blk0 + i;
        gs += g_part[((blk * 2 + 0) * N_FEAT + f) * N_BINS + tid];
        hs += g_part[((blk * 2 + 1) * N_FEAT + f) * N_BINS + tid];
    }
    g_red[(f * 4 + q) * N_BINS + tid] = make_float2(gs, hs);
}

// Stage 2: 100 blocks, reduce 4 quarters + inclusive scan over 256 bins.
__global__ __launch_bounds__(256)
void reduce2_kernel(float* __restrict__ out)
{
    const int f   = blockIdx.x;
    const int tid = threadIdx.x;

    float2 acc = make_float2(0.f, 0.f);
#pragma unroll
    for (int q = 0; q < 4; ++q) {
        float2 v = g_red[(f * 4 + q) * N_BINS + tid];
        acc.x += v.x; acc.y += v.y;
    }

    __shared__ float2 buf[N_BINS];
    buf[tid] = acc;
    __syncthreads();
#pragma unroll
    for (int off = 1; off < N_BINS; off <<= 1) {
        float2 t = make_float2(0.f, 0.f);
        const bool pred = (tid >= off);
        if (pred) t = buf[tid - off];
        __syncthreads();
        if (pred) { buf[tid].x += t.x; buf[tid].y += t.y; }
        __syncthreads();
    }
    float2 r = buf[tid];
    out[f * N_BINS + tid]                   = r.x;   // Gl
    out[N_FEAT * N_BINS + f * N_BINS + tid] = r.y;   // Hl
}

extern "C" void kernel_launch(void* const* d_in, const int* in_sizes, int n_in,
                              void* d_out, int out_size)
{
    const int*   X = (const int*)d_in[0];
    const float* g = (const float*)d_in[1];
    const float* h = (const float*)d_in[2];
    float* out = (float*)d_out;

    (void)cudaFuncSetAttribute(hist_kernel,
                               cudaFuncAttributeMaxDynamicSharedMemorySize, SMEM_BYTES);

    hist_kernel<<<GRID_B, 256, SMEM_BYTES>>>(X, g, h);
    reduce1_kernel<<<N_FEAT * 4, 256>>>();
    reduce2_kernel<<<N_FEAT, 256>>>(out);
}